// round 9
// baseline (speedup 1.0000x reference)
#include <cuda_runtime.h>
#include <cuda_fp16.h>
#include <math.h>
#include <stdint.h>

// Problem constants
#define BB 16
#define QQ 64
#define CC 512
#define DD 512
#define D4 2048
#define MTOT (BB*CC)   // 8192

// Scratch (device globals: allocation-free rule)
__device__ float g_m[BB*CC];
__device__ float g_hp[4*BB*DD];                              // h partials (4-way c-split)
__device__ __align__(16) __half g_Ah[(size_t)MTOT*D4];       // 32 MB
__device__ __align__(16) __half g_Bh[(size_t)D4*D4];         // 8 MB

__device__ __forceinline__ uint32_t smem_u32(const void* p) {
    uint32_t a;
    asm("{ .reg .u64 t; cvta.to.shared.u64 t, %1; cvt.u32.u64 %0, t; }"
        : "=r"(a) : "l"(p));
    return a;
}

#define LDSM4(r, addr) \
    asm volatile("ldmatrix.sync.aligned.m8n8.x4.shared.b16 {%0,%1,%2,%3}, [%4];" \
        : "=r"((r)[0]), "=r"((r)[1]), "=r"((r)[2]), "=r"((r)[3]) : "r"(addr))

#define CP16(dst, src) \
    asm volatile("cp.async.cg.shared.global [%0], [%1], 16;" \
        :: "r"(dst), "l"(src) : "memory")

__device__ __forceinline__ void mma16816(float* d, const uint32_t* a,
                                         uint32_t b0, uint32_t b1) {
    asm volatile(
        "mma.sync.aligned.m16n8k16.row.col.f32.f16.f16.f32 "
        "{%0,%1,%2,%3}, {%4,%5,%6,%7}, {%8,%9}, {%0,%1,%2,%3};"
        : "+f"(d[0]), "+f"(d[1]), "+f"(d[2]), "+f"(d[3])
        : "r"(a[0]), "r"(a[1]), "r"(a[2]), "r"(a[3]), "r"(b0), "r"(b1));
}

__device__ __forceinline__ uint32_t pack2h(float x, float y) {
    __half hx = __float2half_rn(x), hy = __float2half_rn(y);
    return ((uint32_t)__half_as_ushort(hy) << 16) | (uint32_t)__half_as_ushort(hx);
}

// ---------------------------------------------------------------------------
// Kernel 1 (tensorized): per (b, 64-c-tile):
//   phase A: sim[64c x 64q] via mma.sync fp16 (Actx = ctx*w_p fp16, Q fp16)
//   fused row-dots cq/qq during conversion loads
//   softmax (Q=64, block-local) -> P fp16 ; rowmax -> g_m
//   phase C: u[64 x 512] = P @ Q via mma.sync (Qt = d-major Q fp16)
//   writes fp16 seg1 (u) / seg2 (u*ctx) of g_Ah directly.
// 128 blocks (16 b x 8 c-tiles of 64), 256 threads. smem ~207 KB.
// ---------------------------------------------------------------------------
#define RB1 1040      // row stride, 512 fp16 + 8 pad
#define RB2 144       // row stride, 64 fp16 + 8 pad
#define OFF_A  0                       // Actx: 64 x RB1 = 66560
#define OFF_Q  66560                   // Q:    64 x RB1 = 66560
#define OFF_QT 133120                  // Qt:  512 x RB2 = 73728
#define OFF_P  17408                   // P fp16: 64 x RB2 = 9216 (overlaps dead Actx)
#define GSMEM_SIM 206848

__global__ __launch_bounds__(256) void k_sim_u(
    const float* __restrict__ questions,
    const float* __restrict__ contexts,
    const float* __restrict__ sim_w) {
    extern __shared__ char sm[];
    __shared__ float s_cq[64], s_qq[64];
    uint32_t su = smem_u32(sm);
    int b  = blockIdx.x >> 3;
    int ct = blockIdx.x & 7;
    int tid = threadIdx.x;
    int wid = tid >> 5, lane = tid & 31;

    const float* wp  = sim_w + 2*DD;
    const float* wq  = sim_w + DD;
    const float* ctxp = contexts + ((size_t)b*CC + ct*64) * DD;
    const float* qs   = questions + (size_t)b*QQ*DD;

    // ---- load/convert: ctx -> Actx fp16 (fused cq), q -> Q + Qt fp16 (fused qq)
    int row = tid >> 2;          // 0..63
    int f40 = tid & 3;
    float cqp = 0.f, qqp = 0.f;
    #pragma unroll 8
    for (int i = 0; i < 32; i++) {
        int f4 = f40 + i*4;      // 0..127
        float4 v  = *(const float4*)(ctxp + (size_t)row*DD + f4*4);
        float4 wv = *(const float4*)(wp + f4*4);
        float4 wc = *(const float4*)(sim_w + f4*4);
        cqp += v.x*wc.x + v.y*wc.y + v.z*wc.z + v.w*wc.w;
        uint2 h;
        h.x = pack2h(v.x*wv.x, v.y*wv.y);
        h.y = pack2h(v.z*wv.z, v.w*wv.w);
        *(uint2*)(sm + OFF_A + row*RB1 + f4*8) = h;

        float4 q  = *(const float4*)(qs + (size_t)row*DD + f4*4);
        float4 w2 = *(const float4*)(wq + f4*4);
        qqp += q.x*w2.x + q.y*w2.y + q.z*w2.z + q.w*w2.w;
        uint2 hq;
        hq.x = pack2h(q.x, q.y);
        hq.y = pack2h(q.z, q.w);
        *(uint2*)(sm + OFF_Q + row*RB1 + f4*8) = hq;
        // Qt scatter: [d][q]
        int d0 = f4*4;
        *(__half*)(sm + OFF_QT + (d0+0)*RB2 + row*2) = __float2half_rn(q.x);
        *(__half*)(sm + OFF_QT + (d0+1)*RB2 + row*2) = __float2half_rn(q.y);
        *(__half*)(sm + OFF_QT + (d0+2)*RB2 + row*2) = __float2half_rn(q.z);
        *(__half*)(sm + OFF_QT + (d0+3)*RB2 + row*2) = __float2half_rn(q.w);
    }
    {   // reduce 4 lanes per row
        float s = cqp;
        s += __shfl_xor_sync(0xffffffffu, s, 1);
        s += __shfl_xor_sync(0xffffffffu, s, 2);
        if ((tid & 3) == 0) s_cq[row] = s;
        float t2 = qqp;
        t2 += __shfl_xor_sync(0xffffffffu, t2, 1);
        t2 += __shfl_xor_sync(0xffffffffu, t2, 2);
        if ((tid & 3) == 0) s_qq[row] = t2;
    }
    __syncthreads();

    // ---- phase A MMA: sim[64x64], warps 4M x 2N, warp tile 16x32, K=512
    int lr16 = (lane & 7) + ((lane >> 3) & 1) * 8;
    int lc16 = lane >> 4;
    int wmA = wid >> 1;      // 0..3
    int wnA = wid & 1;       // 0..1
    float accA[4][4];
    #pragma unroll
    for (int p = 0; p < 4; p++)
        #pragma unroll
        for (int e = 0; e < 4; e++) accA[p][e] = 0.f;
    {
        uint32_t aB = su + OFF_A + (wmA*16 + lr16)*RB1 + lc16*16;
        uint32_t bB = su + OFF_Q + (wnA*32 + lr16)*RB1 + lc16*16;
        #pragma unroll 4
        for (int kk = 0; kk < 32; kk++) {
            uint32_t af[4], bf[2][4];
            LDSM4(af, aB + kk*32);
            LDSM4(bf[0], bB + kk*32);
            LDSM4(bf[1], bB + 16*RB1 + kk*32);
            #pragma unroll
            for (int p = 0; p < 4; p++)
                mma16816(accA[p], af, bf[p>>1][p&1], bf[p>>1][(p&1)+2]);
        }
    }
    __syncthreads();   // Actx dead; s_sim overlays it

    // ---- phase B: sim -> smem (+cq+qq), softmax, P fp16, rowmax -> g_m
    float* s_sim = (float*)sm;      // [64][66]
    int g = lane >> 2, t = lane & 3;
    #pragma unroll
    for (int p = 0; p < 4; p++) {
        int col = wnA*32 + p*8 + 2*t;
        int r0  = wmA*16 + g;
        s_sim[r0*66 + col]       = accA[p][0] + s_cq[r0]   + s_qq[col];
        s_sim[r0*66 + col + 1]   = accA[p][1] + s_cq[r0]   + s_qq[col+1];
        s_sim[(r0+8)*66 + col]   = accA[p][2] + s_cq[r0+8] + s_qq[col];
        s_sim[(r0+8)*66 + col+1] = accA[p][3] + s_cq[r0+8] + s_qq[col+1];
    }
    __syncthreads();

    #pragma unroll
    for (int rr = 0; rr < 8; rr++) {
        int r = wid*8 + rr;
        float v0 = s_sim[r*66 + lane];
        float v1 = s_sim[r*66 + 32 + lane];
        float mx = fmaxf(v0, v1);
        #pragma unroll
        for (int o = 16; o > 0; o >>= 1) mx = fmaxf(mx, __shfl_xor_sync(0xffffffffu, mx, o));
        float e0 = __expf(v0 - mx), e1 = __expf(v1 - mx);
        float smv = e0 + e1;
        #pragma unroll
        for (int o = 16; o > 0; o >>= 1) smv += __shfl_xor_sync(0xffffffffu, smv, o);
        float inv = 1.f / smv;
        *(__half*)(sm + OFF_P + r*RB2 + lane*2)      = __float2half_rn(e0 * inv);
        *(__half*)(sm + OFF_P + r*RB2 + (lane+32)*2) = __float2half_rn(e1 * inv);
        if (lane == 0) g_m[b*CC + ct*64 + r] = mx;
    }
    __syncthreads();

    // ---- phase C MMA: u[64x512] = P[64x64] @ Qt^T; warp tile 16x128, 2 m-halves
    int wm2 = wid >> 2;      // 0..1
    int wn2 = wid & 3;       // 0..3
    #pragma unroll
    for (int mh = 0; mh < 2; mh++) {
        float accC[8][2][4];
        #pragma unroll
        for (int h = 0; h < 8; h++)
            #pragma unroll
            for (int s2 = 0; s2 < 2; s2++)
                #pragma unroll
                for (int e = 0; e < 4; e++) accC[h][s2][e] = 0.f;
        uint32_t aB = su + OFF_P  + (mh*32 + wm2*16 + lr16)*RB2 + lc16*16;
        uint32_t bB = su + OFF_QT + (wn2*128 + lr16)*RB2 + lc16*16;
        #pragma unroll
        for (int kk = 0; kk < 4; kk++) {
            uint32_t af[4];
            LDSM4(af, aB + kk*32);
            uint32_t bf[8][4];
            #pragma unroll
            for (int h = 0; h < 8; h++)
                LDSM4(bf[h], bB + h*16*RB2 + kk*32);
            #pragma unroll
            for (int h = 0; h < 8; h++) {
                mma16816(accC[h][0], af, bf[h][0], bf[h][2]);
                mma16816(accC[h][1], af, bf[h][1], bf[h][3]);
            }
        }
        // epilogue: seg1 = u fp16, seg2 = u*ctx fp16
        int rl0 = mh*32 + wm2*16 + g;
        size_t mg0 = (size_t)b*CC + ct*64 + rl0;
        #pragma unroll
        for (int h = 0; h < 8; h++) {
            #pragma unroll
            for (int s2 = 0; s2 < 2; s2++) {
                int col = wn2*128 + h*16 + s2*8 + 2*t;
                float* c = accC[h][s2];
                float2 cv0 = *(const float2*)(ctxp + (size_t)rl0*DD + col);
                float2 cv1 = *(const float2*)(ctxp + (size_t)(rl0+8)*DD + col);
                *(uint32_t*)&g_Ah[mg0*D4 + 512  + col] = pack2h(c[0], c[1]);
                *(uint32_t*)&g_Ah[mg0*D4 + 1024 + col] = pack2h(c[0]*cv0.x, c[1]*cv0.y);
                *(uint32_t*)&g_Ah[(mg0+8)*D4 + 512  + col] = pack2h(c[2], c[3]);
                *(uint32_t*)&g_Ah[(mg0+8)*D4 + 1024 + col] = pack2h(c[2]*cv1.x, c[3]*cv1.y);
            }
        }
    }
}

// ---------------------------------------------------------------------------
// Kernel 2: h_tilde partials with fused attn softmax
// 512 blocks (b x 8 dchunk x 4 csplit) x 128 thr
// ---------------------------------------------------------------------------
__global__ void k_h(const float* __restrict__ contexts) {
    __shared__ float smm[512];
    __shared__ float red[128];
    __shared__ float sa[128];
    __shared__ float part[128];
    int bid = blockIdx.x;
    int cs = bid & 3;
    int dc = (bid >> 2) & 7;
    int b  = bid >> 5;
    int tid = threadIdx.x;
    #pragma unroll
    for (int i = 0; i < 4; i++) smm[tid + i*128] = g_m[b*CC + tid + i*128];
    __syncthreads();
    float mx = fmaxf(fmaxf(smm[tid], smm[tid+128]), fmaxf(smm[tid+256], smm[tid+384]));
    red[tid] = mx; __syncthreads();
    for (int s = 64; s > 0; s >>= 1) {
        if (tid < s) red[tid] = fmaxf(red[tid], red[tid + s]);
        __syncthreads();
    }
    mx = red[0]; __syncthreads();
    float sv = __expf(smm[tid]-mx) + __expf(smm[tid+128]-mx)
             + __expf(smm[tid+256]-mx) + __expf(smm[tid+384]-mx);
    red[tid] = sv; __syncthreads();
    for (int s = 64; s > 0; s >>= 1) {
        if (tid < s) red[tid] += red[tid + s];
        __syncthreads();
    }
    float inv = 1.f / red[0];
    sa[tid] = __expf(smm[cs*128 + tid] - mx) * inv;
    __syncthreads();
    int d = dc*64 + (tid & 63);
    int h = tid >> 6;
    const float* ctx = contexts + ((size_t)b*CC + cs*128 + h*64)*DD;
    float acc = 0.f;
    #pragma unroll 8
    for (int c = 0; c < 64; c++) acc += sa[h*64 + c] * ctx[(size_t)c*DD + d];
    part[tid] = acc;
    __syncthreads();
    if (h == 0) g_hp[((size_t)b*4 + cs)*DD + d] = part[tid] + part[tid + 64];
}

// ---------------------------------------------------------------------------
// Kernel 3: A seg0/seg3 -> fp16, and qac_w -> fp16 (merged)   [R8, unchanged]
// ---------------------------------------------------------------------------
__global__ void k_mm(const float* __restrict__ contexts,
                     const float* __restrict__ qac_w) {
    int bid = blockIdx.x;
    int tid = threadIdx.x;
    if (bid < 8192) {
        int m = bid;
        int b = m >> 9;
        uint2 h4;
        if (tid < 128) {
            int off = tid*4;
            float4 cv = *(const float4*)(contexts + (size_t)m*DD + off);
            h4.x = pack2h(cv.x, cv.y);
            h4.y = pack2h(cv.z, cv.w);
            *(uint2*)&g_Ah[(size_t)m*D4 + off] = h4;
        } else {
            int off = (tid - 128)*4;
            float4 cv = *(const float4*)(contexts + (size_t)m*DD + off);
            const float* hp = g_hp + (size_t)b*4*DD + off;
            float4 h0 = *(const float4*)(hp);
            float4 h1 = *(const float4*)(hp + DD);
            float4 h2 = *(const float4*)(hp + 2*DD);
            float4 h3 = *(const float4*)(hp + 3*DD);
            float hx = h0.x+h1.x+h2.x+h3.x;
            float hy = h0.y+h1.y+h2.y+h3.y;
            float hz = h0.z+h1.z+h2.z+h3.z;
            float hw = h0.w+h1.w+h2.w+h3.w;
            h4.x = pack2h(cv.x*hx, cv.y*hy);
            h4.y = pack2h(cv.z*hz, cv.w*hw);
            *(uint2*)&g_Ah[(size_t)m*D4 + 1536 + off] = h4;
        }
    } else {
        size_t i4 = (size_t)(bid - 8192)*256 + tid;   // D4*D4/4
        float4 v = ((const float4*)qac_w)[i4];
        uint2 h4;
        h4.x = pack2h(v.x, v.y);
        h4.y = pack2h(v.z, v.w);
        ((uint2*)g_Bh)[i4] = h4;
    }
}

// ---------------------------------------------------------------------------
// Kernel 4: mma.sync fp16 GEMM (single term, K = 2048)  [R7, unchanged]
// ---------------------------------------------------------------------------
#define ROWB 144
#define ATILE (128*ROWB)         // 18432 B
#define STG1B (2*ATILE)          // 36864 B per stage (A|B)
#define GSMEM2 (3*STG1B)         // 110592 B

__global__ __launch_bounds__(256, 2) void k_gemm_mma(
    const float* __restrict__ bias, float* __restrict__ out) {
    extern __shared__ char smem[];
    uint32_t su = smem_u32(smem);
    int tid  = threadIdx.x;
    int lane = tid & 31;
    int w    = tid >> 5;
    int wm   = w >> 2;          // 0..1
    int wn   = w & 3;           // 0..3
    int n0 = blockIdx.x * 128;
    int m0 = blockIdx.y * 128;

    float acc[4][4][4];
    #pragma unroll
    for (int i = 0; i < 4; i++)
        #pragma unroll
        for (int p = 0; p < 4; p++)
            #pragma unroll
            for (int e = 0; e < 4; e++) acc[i][p][e] = 0.f;

    int lrow = tid >> 3;        // 0..31
    int lchk = tid & 7;         // 16B chunk within 128B row

    auto load_stage = [&](int it, int s) {
        int kbase = it * 64;
        uint32_t sb = su + s*STG1B;
        #pragma unroll
        for (int i = 0; i < 4; i++) {
            int row = lrow + i*32;
            size_t aoff = (size_t)(m0 + row)*D4 + kbase + lchk*8;
            size_t boff = (size_t)(n0 + row)*D4 + kbase + lchk*8;
            uint32_t d = sb + row*ROWB + lchk*16;
            CP16(d,         (const void*)(g_Ah + aoff));
            CP16(d + ATILE, (const void*)(g_Bh + boff));
        }
        asm volatile("cp.async.commit_group;" ::: "memory");
    };

    load_stage(0, 0);
    load_stage(1, 1);

    int lr16 = (lane & 7) + ((lane >> 3) & 1) * 8;   // row 0..15
    int lc16 = lane >> 4;                             // chunk 0/1

    for (int it = 0; it < 32; it++) {
        int s = it % 3;
        if (it < 31) {
            asm volatile("cp.async.wait_group %0;" :: "n"(1) : "memory");
        } else {
            asm volatile("cp.async.wait_group %0;" :: "n"(0) : "memory");
        }
        __syncthreads();

        if (it + 2 < 32) load_stage(it + 2, (it + 2) % 3);

        uint32_t base = su + s*STG1B;
        uint32_t aW = base + (wm*64 + lr16)*ROWB + lc16*16;
        uint32_t bW = base + ATILE + (wn*32 + lr16)*ROWB + lc16*16;

        #pragma unroll
        for (int j = 0; j < 4; j++) {
            uint32_t af[4][4];
            #pragma unroll
            for (int i = 0; i < 4; i++)
                LDSM4(af[i], aW + i*16*ROWB + j*32);
            uint32_t bf[2][4];
            #pragma unroll
            for (int h = 0; h < 2; h++)
                LDSM4(bf[h], bW + h*16*ROWB + j*32);
            #pragma unroll
            for (int i = 0; i < 4; i++)
                #pragma unroll
                for (int p = 0; p < 4; p++)
                    mma16816(acc[i][p], af[i], bf[p>>1][p&1], bf[p>>1][(p&1)+2]);
        }
    }

    // Epilogue
    int g = lane >> 2, t = lane & 3;
    #pragma unroll
    for (int i = 0; i < 4; i++) {
        int row = m0 + wm*64 + i*16 + g;
        #pragma unroll
        for (int p = 0; p < 4; p++) {
            int col = n0 + wn*32 + p*8 + 2*t;
            float b0 = bias[col], b1 = bias[col + 1];
            float2 v0 = make_float2(acc[i][p][0] + b0, acc[i][p][1] + b1);
            float2 v1 = make_float2(acc[i][p][2] + b0, acc[i][p][3] + b1);
            *(float2*)(out + (size_t)row*D4 + col)       = v0;
            *(float2*)(out + (size_t)(row + 8)*D4 + col) = v1;
        }
    }
}

// ---------------------------------------------------------------------------
extern "C" void kernel_launch(void* const* d_in, const int* in_sizes, int n_in,
                              void* d_out, int out_size) {
    const float* questions = (const float*)d_in[0];
    const float* contexts  = (const float*)d_in[1];
    const float* sim_w     = (const float*)d_in[2];
    const float* qac_w     = (const float*)d_in[3];
    const float* qac_b     = (const float*)d_in[4];
    float* out = (float*)d_out;

    cudaFuncSetAttribute(k_sim_u, cudaFuncAttributeMaxDynamicSharedMemorySize, GSMEM_SIM);
    cudaFuncSetAttribute(k_gemm_mma, cudaFuncAttributeMaxDynamicSharedMemorySize, GSMEM2);

    k_sim_u<<<128, 256, GSMEM_SIM>>>(questions, contexts, sim_w);
    k_h<<<512, 128>>>(contexts);
    k_mm<<<12288, 256>>>(contexts, qac_w);
    k_gemm_mma<<<dim3(16, 64), 256, GSMEM2>>>(qac_b, out);
}

// round 10
// speedup vs baseline: 1.3019x; 1.3019x over previous
#include <cuda_runtime.h>
#include <cuda_fp16.h>
#include <math.h>
#include <stdint.h>

// Problem constants
#define BB 16
#define QQ 64
#define CC 512
#define DD 512
#define D4 2048
#define MTOT (BB*CC)   // 8192

// Scratch (device globals: allocation-free rule)
__device__ float g_m[BB*CC];
__device__ float g_hp[4*BB*DD];                              // h partials (4-way c-split)
__device__ __align__(16) __half g_Ah[(size_t)MTOT*D4];       // 32 MB
__device__ __align__(16) __half g_Bh[(size_t)D4*D4];         // 8 MB

__device__ __forceinline__ uint32_t smem_u32(const void* p) {
    uint32_t a;
    asm("{ .reg .u64 t; cvta.to.shared.u64 t, %1; cvt.u32.u64 %0, t; }"
        : "=r"(a) : "l"(p));
    return a;
}

#define LDSM4(r, addr) \
    asm volatile("ldmatrix.sync.aligned.m8n8.x4.shared.b16 {%0,%1,%2,%3}, [%4];" \
        : "=r"((r)[0]), "=r"((r)[1]), "=r"((r)[2]), "=r"((r)[3]) : "r"(addr))

#define CP16(dst, src) \
    asm volatile("cp.async.cg.shared.global [%0], [%1], 16;" \
        :: "r"(dst), "l"(src) : "memory")

__device__ __forceinline__ void mma16816(float* d, const uint32_t* a,
                                         uint32_t b0, uint32_t b1) {
    asm volatile(
        "mma.sync.aligned.m16n8k16.row.col.f32.f16.f16.f32 "
        "{%0,%1,%2,%3}, {%4,%5,%6,%7}, {%8,%9}, {%0,%1,%2,%3};"
        : "+f"(d[0]), "+f"(d[1]), "+f"(d[2]), "+f"(d[3])
        : "r"(a[0]), "r"(a[1]), "r"(a[2]), "r"(a[3]), "r"(b0), "r"(b1));
}

__device__ __forceinline__ uint32_t pack2h(float x, float y) {
    __half hx = __float2half_rn(x), hy = __float2half_rn(y);
    return ((uint32_t)__half_as_ushort(hy) << 16) | (uint32_t)__half_as_ushort(hx);
}

// ---------------------------------------------------------------------------
// Kernel 1: per (b, 32-c-tile): sim tile (+fused row-dots) + softmax + u_tilde
// writes u (seg1) and u*ctx (seg2) of g_Ah directly as fp16.  [R8 proven]
// 256 blocks (16 b x 16 c-tiles), 256 threads
// ---------------------------------------------------------------------------
__global__ __launch_bounds__(256) void k_sim_u(
    const float* __restrict__ questions,
    const float* __restrict__ contexts,
    const float* __restrict__ sim_w) {
    __shared__ float sh[2112 + 4352];
    __shared__ float s_cq[32], s_qq[64];
    int b  = blockIdx.x >> 4;
    int ct = blockIdx.x & 15;
    int tid = threadIdx.x;
    int tx = tid & 15, ty = tid >> 4;     // ty 0..15 -> 2 c-rows; tx -> 4 q-cols
    int wid = tid >> 5, lane = tid & 31;

    const float* wp  = sim_w + 2*DD;
    const float* wq  = sim_w + DD;
    const float* ctx = contexts + ((size_t)b*CC + ct*32) * DD;
    const float* qs  = questions + (size_t)b*QQ*DD;

    float acc[2][4];
    #pragma unroll
    for (int i = 0; i < 2; i++)
        #pragma unroll
        for (int j = 0; j < 4; j++) acc[i][j] = 0.f;

    float* s_a = sh;            // [32k][32row]
    float* s_b = sh + 1024;     // [32k][64row]

    float cqp = 0.f;            // partial ctx . w_c   (row = tid>>3, kq = tid&7)
    float qqp = 0.f;            // partial q . w_q     (row = tid>>2)

    // Phase A: sim[32c x 64q], K=512 in chunks of 32; row-dots fused into loads
    for (int k0 = 0; k0 < DD; k0 += 32) {
        __syncthreads();
        {   // A: 32 rows x 8 float4 (one per thread)
            int row = tid >> 3, kq = tid & 7;
            float4 av = *(const float4*)(ctx + (size_t)row*DD + k0 + kq*4);
            float4 wv = *(const float4*)(wp + k0 + kq*4);
            float4 wc = *(const float4*)(sim_w + k0 + kq*4);
            cqp += av.x*wc.x + av.y*wc.y + av.z*wc.z + av.w*wc.w;
            s_a[(kq*4+0)*32 + row] = av.x * wv.x;
            s_a[(kq*4+1)*32 + row] = av.y * wv.y;
            s_a[(kq*4+2)*32 + row] = av.z * wv.z;
            s_a[(kq*4+3)*32 + row] = av.w * wv.w;
        }
        #pragma unroll
        for (int i = 0; i < 2; i++) {   // B: 64 rows x 8 float4
            int li = tid*2 + i;
            int row = li >> 3, kq = li & 7;
            float4 qv = *(const float4*)(qs + (size_t)row*DD + k0 + kq*4);
            float4 wv = *(const float4*)(wq + k0 + kq*4);
            qqp += qv.x*wv.x + qv.y*wv.y + qv.z*wv.z + qv.w*wv.w;
            s_b[(kq*4+0)*64 + row] = qv.x;
            s_b[(kq*4+1)*64 + row] = qv.y;
            s_b[(kq*4+2)*64 + row] = qv.z;
            s_b[(kq*4+3)*64 + row] = qv.w;
        }
        __syncthreads();
        #pragma unroll
        for (int k = 0; k < 32; k++) {
            float2 av = *(float2*)&s_a[k*32 + ty*2];
            float4 bv = *(float4*)&s_b[k*64 + tx*4];
            float b4[4] = {bv.x, bv.y, bv.z, bv.w};
            #pragma unroll
            for (int j = 0; j < 4; j++) {
                acc[0][j] += av.x * b4[j];
                acc[1][j] += av.y * b4[j];
            }
        }
    }

    // Reduce fused row-dots: cq (8 lanes/row), qq (4 lanes/row)
    {
        float s = cqp;
        s += __shfl_xor_sync(0xffffffffu, s, 1);
        s += __shfl_xor_sync(0xffffffffu, s, 2);
        s += __shfl_xor_sync(0xffffffffu, s, 4);
        if ((tid & 7) == 0) s_cq[tid >> 3] = s;
        float t = qqp;
        t += __shfl_xor_sync(0xffffffffu, t, 1);
        t += __shfl_xor_sync(0xffffffffu, t, 2);
        if ((tid & 3) == 0) s_qq[tid >> 2] = t;
    }
    __syncthreads();

    // Phase B: add cq/qq, write sim, per-row softmax (Q=64), rowmax -> g_m
    float* s_sim = sh;          // [32][66]
    #pragma unroll
    for (int i = 0; i < 2; i++) {
        float cqv = s_cq[ty*2 + i];
        #pragma unroll
        for (int j = 0; j < 4; j++)
            s_sim[(ty*2+i)*66 + tx*4 + j] = acc[i][j] + cqv + s_qq[tx*4 + j];
    }
    __syncthreads();

    #pragma unroll
    for (int rr = 0; rr < 4; rr++) {
        int r = wid*4 + rr;
        float v0 = s_sim[r*66 + lane];
        float v1 = s_sim[r*66 + 32 + lane];
        float mx = fmaxf(v0, v1);
        #pragma unroll
        for (int o = 16; o > 0; o >>= 1) mx = fmaxf(mx, __shfl_xor_sync(0xffffffffu, mx, o));
        float e0 = __expf(v0 - mx), e1 = __expf(v1 - mx);
        float sm = e0 + e1;
        #pragma unroll
        for (int o = 16; o > 0; o >>= 1) sm += __shfl_xor_sync(0xffffffffu, sm, o);
        float inv = 1.f / sm;
        s_sim[r*66 + lane]      = e0 * inv;
        s_sim[r*66 + 32 + lane] = e1 * inv;
        if (lane == 0) g_m[b*CC + ct*32 + r] = mx;
    }
    __syncthreads();

    // Phase C: u[32 x 512] = P[32x64] @ qs[64x512]; write fp16 seg1/seg2 of A
    float* s_q2 = sh + 2112;    // [64][68]
    for (int d0 = 0; d0 < DD; d0 += 64) {
        #pragma unroll
        for (int i = 0; i < 4; i++) {
            int li  = tid + i*256;
            int row = li >> 4;
            int dq  = li & 15;
            float4 qv = *(const float4*)(qs + (size_t)row*DD + d0 + dq*4);
            *(float4*)&s_q2[row*68 + dq*4] = qv;
        }
        __syncthreads();
        float a2[2][4];
        #pragma unroll
        for (int i = 0; i < 2; i++)
            #pragma unroll
            for (int j = 0; j < 4; j++) a2[i][j] = 0.f;
        #pragma unroll 8
        for (int k = 0; k < 64; k++) {
            float p0 = s_sim[(ty*2+0)*66 + k];
            float p1 = s_sim[(ty*2+1)*66 + k];
            float4 qv = *(float4*)&s_q2[k*68 + tx*4];
            float q4[4] = {qv.x, qv.y, qv.z, qv.w};
            #pragma unroll
            for (int j = 0; j < 4; j++) {
                a2[0][j] += p0 * q4[j];
                a2[1][j] += p1 * q4[j];
            }
        }
        #pragma unroll
        for (int i = 0; i < 2; i++) {
            int lrow = ty*2 + i;
            size_t m = (size_t)b*CC + ct*32 + lrow;
            float4 cv = *(const float4*)(ctx + (size_t)lrow*DD + d0 + tx*4);
            uint2 uh, uc;
            uh.x = pack2h(a2[i][0], a2[i][1]);
            uh.y = pack2h(a2[i][2], a2[i][3]);
            uc.x = pack2h(a2[i][0]*cv.x, a2[i][1]*cv.y);
            uc.y = pack2h(a2[i][2]*cv.z, a2[i][3]*cv.w);
            *(uint2*)&g_Ah[m*D4 + 512  + d0 + tx*4] = uh;
            *(uint2*)&g_Ah[m*D4 + 1024 + d0 + tx*4] = uc;
        }
        __syncthreads();
    }
}

// ---------------------------------------------------------------------------
// Kernel 2: h_tilde partials with fused attn softmax  [R9, kept]
// 512 blocks (b x 8 dchunk x 4 csplit) x 128 thr
// ---------------------------------------------------------------------------
__global__ void k_h(const float* __restrict__ contexts) {
    __shared__ float smm[512];
    __shared__ float red[128];
    __shared__ float sa[128];
    __shared__ float part[128];
    int bid = blockIdx.x;
    int cs = bid & 3;
    int dc = (bid >> 2) & 7;
    int b  = bid >> 5;
    int tid = threadIdx.x;
    #pragma unroll
    for (int i = 0; i < 4; i++) smm[tid + i*128] = g_m[b*CC + tid + i*128];
    __syncthreads();
    float mx = fmaxf(fmaxf(smm[tid], smm[tid+128]), fmaxf(smm[tid+256], smm[tid+384]));
    red[tid] = mx; __syncthreads();
    for (int s = 64; s > 0; s >>= 1) {
        if (tid < s) red[tid] = fmaxf(red[tid], red[tid + s]);
        __syncthreads();
    }
    mx = red[0]; __syncthreads();
    float sv = __expf(smm[tid]-mx) + __expf(smm[tid+128]-mx)
             + __expf(smm[tid+256]-mx) + __expf(smm[tid+384]-mx);
    red[tid] = sv; __syncthreads();
    for (int s = 64; s > 0; s >>= 1) {
        if (tid < s) red[tid] += red[tid + s];
        __syncthreads();
    }
    float inv = 1.f / red[0];
    sa[tid] = __expf(smm[cs*128 + tid] - mx) * inv;
    __syncthreads();
    int d = dc*64 + (tid & 63);
    int h = tid >> 6;
    const float* ctx = contexts + ((size_t)b*CC + cs*128 + h*64)*DD;
    float acc = 0.f;
    #pragma unroll 8
    for (int c = 0; c < 64; c++) acc += sa[h*64 + c] * ctx[(size_t)c*DD + d];
    part[tid] = acc;
    __syncthreads();
    if (h == 0) g_hp[((size_t)b*4 + cs)*DD + d] = part[tid] + part[tid + 64];
}

// ---------------------------------------------------------------------------
// Kernel 3: A seg0/seg3 -> fp16, and qac_w -> fp16 (merged)   [R8, unchanged]
// ---------------------------------------------------------------------------
__global__ void k_mm(const float* __restrict__ contexts,
                     const float* __restrict__ qac_w) {
    int bid = blockIdx.x;
    int tid = threadIdx.x;
    if (bid < 8192) {
        int m = bid;
        int b = m >> 9;
        uint2 h4;
        if (tid < 128) {
            int off = tid*4;
            float4 cv = *(const float4*)(contexts + (size_t)m*DD + off);
            h4.x = pack2h(cv.x, cv.y);
            h4.y = pack2h(cv.z, cv.w);
            *(uint2*)&g_Ah[(size_t)m*D4 + off] = h4;
        } else {
            int off = (tid - 128)*4;
            float4 cv = *(const float4*)(contexts + (size_t)m*DD + off);
            const float* hp = g_hp + (size_t)b*4*DD + off;
            float4 h0 = *(const float4*)(hp);
            float4 h1 = *(const float4*)(hp + DD);
            float4 h2 = *(const float4*)(hp + 2*DD);
            float4 h3 = *(const float4*)(hp + 3*DD);
            float hx = h0.x+h1.x+h2.x+h3.x;
            float hy = h0.y+h1.y+h2.y+h3.y;
            float hz = h0.z+h1.z+h2.z+h3.z;
            float hw = h0.w+h1.w+h2.w+h3.w;
            h4.x = pack2h(cv.x*hx, cv.y*hy);
            h4.y = pack2h(cv.z*hz, cv.w*hw);
            *(uint2*)&g_Ah[(size_t)m*D4 + 1536 + off] = h4;
        }
    } else {
        size_t i4 = (size_t)(bid - 8192)*256 + tid;   // D4*D4/4
        float4 v = ((const float4*)qac_w)[i4];
        uint2 h4;
        h4.x = pack2h(v.x, v.y);
        h4.y = pack2h(v.z, v.w);
        ((uint2*)g_Bh)[i4] = h4;
    }
}

// ---------------------------------------------------------------------------
// Kernel 4: mma.sync fp16 GEMM (single term, K = 2048)  [R7, unchanged]
// ---------------------------------------------------------------------------
#define ROWB 144
#define ATILE (128*ROWB)         // 18432 B
#define STG1B (2*ATILE)          // 36864 B per stage (A|B)
#define GSMEM2 (3*STG1B)         // 110592 B

__global__ __launch_bounds__(256, 2) void k_gemm_mma(
    const float* __restrict__ bias, float* __restrict__ out) {
    extern __shared__ char smem[];
    uint32_t su = smem_u32(smem);
    int tid  = threadIdx.x;
    int lane = tid & 31;
    int w    = tid >> 5;
    int wm   = w >> 2;          // 0..1
    int wn   = w & 3;           // 0..3
    int n0 = blockIdx.x * 128;
    int m0 = blockIdx.y * 128;

    float acc[4][4][4];
    #pragma unroll
    for (int i = 0; i < 4; i++)
        #pragma unroll
        for (int p = 0; p < 4; p++)
            #pragma unroll
            for (int e = 0; e < 4; e++) acc[i][p][e] = 0.f;

    int lrow = tid >> 3;        // 0..31
    int lchk = tid & 7;         // 16B chunk within 128B row

    auto load_stage = [&](int it, int s) {
        int kbase = it * 64;
        uint32_t sb = su + s*STG1B;
        #pragma unroll
        for (int i = 0; i < 4; i++) {
            int row = lrow + i*32;
            size_t aoff = (size_t)(m0 + row)*D4 + kbase + lchk*8;
            size_t boff = (size_t)(n0 + row)*D4 + kbase + lchk*8;
            uint32_t d = sb + row*ROWB + lchk*16;
            CP16(d,         (const void*)(g_Ah + aoff));
            CP16(d + ATILE, (const void*)(g_Bh + boff));
        }
        asm volatile("cp.async.commit_group;" ::: "memory");
    };

    load_stage(0, 0);
    load_stage(1, 1);

    int lr16 = (lane & 7) + ((lane >> 3) & 1) * 8;   // row 0..15
    int lc16 = lane >> 4;                             // chunk 0/1

    for (int it = 0; it < 32; it++) {
        int s = it % 3;
        if (it < 31) {
            asm volatile("cp.async.wait_group %0;" :: "n"(1) : "memory");
        } else {
            asm volatile("cp.async.wait_group %0;" :: "n"(0) : "memory");
        }
        __syncthreads();

        if (it + 2 < 32) load_stage(it + 2, (it + 2) % 3);

        uint32_t base = su + s*STG1B;
        uint32_t aW = base + (wm*64 + lr16)*ROWB + lc16*16;
        uint32_t bW = base + ATILE + (wn*32 + lr16)*ROWB + lc16*16;

        #pragma unroll
        for (int j = 0; j < 4; j++) {
            uint32_t af[4][4];
            #pragma unroll
            for (int i = 0; i < 4; i++)
                LDSM4(af[i], aW + i*16*ROWB + j*32);
            uint32_t bf[2][4];
            #pragma unroll
            for (int h = 0; h < 2; h++)
                LDSM4(bf[h], bW + h*16*ROWB + j*32);
            #pragma unroll
            for (int i = 0; i < 4; i++)
                #pragma unroll
                for (int p = 0; p < 4; p++)
                    mma16816(acc[i][p], af[i], bf[p>>1][p&1], bf[p>>1][(p&1)+2]);
        }
    }

    // Epilogue
    int g = lane >> 2, t = lane & 3;
    #pragma unroll
    for (int i = 0; i < 4; i++) {
        int row = m0 + wm*64 + i*16 + g;
        #pragma unroll
        for (int p = 0; p < 4; p++) {
            int col = n0 + wn*32 + p*8 + 2*t;
            float b0 = bias[col], b1 = bias[col + 1];
            float2 v0 = make_float2(acc[i][p][0] + b0, acc[i][p][1] + b1);
            float2 v1 = make_float2(acc[i][p][2] + b0, acc[i][p][3] + b1);
            *(float2*)(out + (size_t)row*D4 + col)       = v0;
            *(float2*)(out + (size_t)(row + 8)*D4 + col) = v1;
        }
    }
}

// ---------------------------------------------------------------------------
extern "C" void kernel_launch(void* const* d_in, const int* in_sizes, int n_in,
                              void* d_out, int out_size) {
    const float* questions = (const float*)d_in[0];
    const float* contexts  = (const float*)d_in[1];
    const float* sim_w     = (const float*)d_in[2];
    const float* qac_w     = (const float*)d_in[3];
    const float* qac_b     = (const float*)d_in[4];
    float* out = (float*)d_out;

    cudaFuncSetAttribute(k_gemm_mma, cudaFuncAttributeMaxDynamicSharedMemorySize, GSMEM2);

    k_sim_u<<<256, 256>>>(questions, contexts, sim_w);
    k_h<<<512, 128>>>(contexts);
    k_mm<<<12288, 256>>>(contexts, qac_w);
    k_gemm_mma<<<dim3(16, 64), 256, GSMEM2>>>(qac_b, out);
}